// round 11
// baseline (speedup 1.0000x reference)
#include <cuda_runtime.h>
#include <stdint.h>

#define D 128
#define MAX_NODES 100000
#define MAX_EDGES 1700000
#define NSM 148
#define GBM 128
#define AST 129
#define ASZ (D * AST)

__device__ float g_y[MAX_NODES * D];      // 51.2 MB
__device__ int   g_bad;                   // nonzero -> edge_index int32
__device__ int   g_hist[MAX_NODES];       // per-src counts
__device__ int   g_cursor[MAX_NODES];     // scan result / scatter cursor
__device__ int4  g_sorted[MAX_EDGES];     // (src, dst, eid, 0)

// ---------------------------------------------------------------------------
// helpers
// ---------------------------------------------------------------------------
__device__ __forceinline__ void ldg_el32B(const float* p, float4& lo, float4& hi) {
    unsigned long long x0, x1, x2, x3;
    asm volatile("ld.global.nc.L2::evict_last.v4.b64 {%0,%1,%2,%3}, [%4];"
                 : "=l"(x0), "=l"(x1), "=l"(x2), "=l"(x3) : "l"(p));
    lo.x = __uint_as_float((unsigned)x0); lo.y = __uint_as_float((unsigned)(x0 >> 32));
    lo.z = __uint_as_float((unsigned)x1); lo.w = __uint_as_float((unsigned)(x1 >> 32));
    hi.x = __uint_as_float((unsigned)x2); hi.y = __uint_as_float((unsigned)(x2 >> 32));
    hi.z = __uint_as_float((unsigned)x3); hi.w = __uint_as_float((unsigned)(x3 >> 32));
}
__device__ __forceinline__ void stg_el32B(float* p, unsigned long long x0,
                                          unsigned long long x1,
                                          unsigned long long x2,
                                          unsigned long long x3) {
    asm volatile("st.global.L2::evict_last.v4.b64 [%0], {%1,%2,%3,%4};"
                 :: "l"(p), "l"(x0), "l"(x1), "l"(x2), "l"(x3) : "memory");
}
__device__ __forceinline__ void cp_async4(uint32_t smem_addr, const float* gptr) {
    asm volatile("cp.async.ca.shared.global [%0], [%1], 4;"
                 :: "r"(smem_addr), "l"(gptr));
}

// ---------------------------------------------------------------------------
// K0: zero histogram + detect index dtype
// ---------------------------------------------------------------------------
__global__ void init_k(const unsigned int* __restrict__ ei_raw, int nwords, int n)
{
    int gt = blockIdx.x * blockDim.x + threadIdx.x;
    for (int i = gt; i < n; i += gridDim.x * blockDim.x)
        g_hist[i] = 0;
    if (blockIdx.x == 0) {
        __shared__ int bad;
        if (threadIdx.x == 0) bad = 0;
        __syncthreads();
        int limit = 1024;
        if (limit > nwords) limit = nwords & ~1;
        for (int i = threadIdx.x; i * 2 + 1 < limit; i += blockDim.x)
            if (ei_raw[i * 2 + 1] != 0u) atomicOr(&bad, 1);
        __syncthreads();
        if (threadIdx.x == 0) g_bad = bad;
    }
}

// ---------------------------------------------------------------------------
// K1: histogram of src
// ---------------------------------------------------------------------------
__global__ void hist_k(const void* __restrict__ ei, int E)
{
    const int bad = g_bad;
    int gt = blockIdx.x * blockDim.x + threadIdx.x;
    int stride = gridDim.x * blockDim.x;
    for (int e = gt; e < E; e += stride) {
        int s = bad ? ((const int*)ei)[e]
                    : (int)((const long long*)ei)[e];
        atomicAdd(&g_hist[s], 1);
    }
}

// ---------------------------------------------------------------------------
// K2: exclusive scan of histogram -> g_cursor (single block, 1024 threads)
// ---------------------------------------------------------------------------
__global__ void __launch_bounds__(1024) scan_k(int n)
{
    __shared__ int part[1024];
    const int tid = threadIdx.x;
    const int chunk = (n + 1023) >> 10;
    int lo = tid * chunk;
    int hi = lo + chunk; if (hi > n) hi = n; if (lo > n) lo = n;

    int s = 0;
    for (int i = lo; i < hi; i++) s += g_hist[i];
    part[tid] = s;
    __syncthreads();
    #pragma unroll
    for (int off = 1; off < 1024; off <<= 1) {
        int v = (tid >= off) ? part[tid - off] : 0;
        __syncthreads();
        part[tid] += v;
        __syncthreads();
    }
    int run = part[tid] - s;     // exclusive prefix
    for (int i = lo; i < hi; i++) {
        g_cursor[i] = run;
        run += g_hist[i];
    }
}

// ---------------------------------------------------------------------------
// K3: scatter edges into src-sorted order
// ---------------------------------------------------------------------------
__global__ void scatter_k(const void* __restrict__ ei, int E)
{
    const int bad = g_bad;
    int gt = blockIdx.x * blockDim.x + threadIdx.x;
    int stride = gridDim.x * blockDim.x;
    for (int e = gt; e < E; e += stride) {
        int s, d;
        if (bad) {
            const int* p = (const int*)ei;
            s = p[e]; d = p[E + e];
        } else {
            const long long* p = (const long long*)ei;
            s = (int)p[e]; d = (int)p[(long long)E + e];
        }
        int pos = atomicAdd(&g_cursor[s], 1);
        g_sorted[pos] = make_int4(s, d, e, 0);
    }
}

// ---------------------------------------------------------------------------
// K4: persistent GEMM (R8 config): 148 CTAs x 512 thr, W in smem, A tiles
// double-buffered; thread = 2 rows x 16 cols (16 packed f32x2 accumulators).
// ---------------------------------------------------------------------------
__global__ void __launch_bounds__(512, 1) gemm_xout_w(
    const float* __restrict__ x_out,
    const float* __restrict__ W,
    int n)
{
    extern __shared__ float smem[];
    float* Ws = smem;
    float* As = smem + D * D;

    const int tid    = threadIdx.x;
    const int bid    = blockIdx.x;
    const int ntiles = (n + GBM - 1) / GBM;

    #pragma unroll
    for (int i = tid; i < (D * D) / 4; i += 512)
        ((float4*)Ws)[i] = ((const float4*)W)[i];

    uint32_t as_base;
    asm("{ .reg .u64 t; cvta.to.shared.u64 t, %1; cvt.u32.u64 %0, t; }"
        : "=r"(as_base) : "l"(As));

    const int kS = tid & 127;
    const int rS = tid >> 7;

    if (bid < ntiles) {
        #pragma unroll
        for (int p = 0; p < 32; p++) {
            int rr = p * 4 + rS;
            int grow = bid * GBM + rr;
            if (grow >= n) grow = n - 1;
            cp_async4(as_base + (uint32_t)(kS * AST + rr) * 4,
                      &x_out[(size_t)grow * D + kS]);
        }
        asm volatile("cp.async.commit_group;");
    }

    const int r0 = tid & 63;
    const int cg = tid >> 6;

    int buf = 0;
    for (int t = bid; t < ntiles; t += NSM) {
        bool has_next = (t + NSM) < ntiles;
        if (has_next) {
            int tn = t + NSM;
            uint32_t dstb = as_base + (uint32_t)((buf ^ 1) * ASZ) * 4;
            #pragma unroll
            for (int p = 0; p < 32; p++) {
                int rr = p * 4 + rS;
                int grow = tn * GBM + rr;
                if (grow >= n) grow = n - 1;
                cp_async4(dstb + (uint32_t)(kS * AST + rr) * 4,
                          &x_out[(size_t)grow * D + kS]);
            }
            asm volatile("cp.async.commit_group;");
            asm volatile("cp.async.wait_group 1;");
        } else {
            asm volatile("cp.async.wait_group 0;");
        }
        __syncthreads();

        const float* A = As + buf * ASZ;
        unsigned long long acc[16];
        #pragma unroll
        for (int j = 0; j < 16; j++) acc[j] = 0ull;

        #pragma unroll 8
        for (int kk = 0; kk < D; kk++) {
            float a0 = A[kk * AST + r0];
            float a1 = A[kk * AST + r0 + 64];
            unsigned long long aa0, aa1;
            asm("mov.b64 %0, {%1, %1};" : "=l"(aa0) : "r"(__float_as_uint(a0)));
            asm("mov.b64 %0, {%1, %1};" : "=l"(aa1) : "r"(__float_as_uint(a1)));
            const ulonglong2* wp = reinterpret_cast<const ulonglong2*>(&Ws[kk * D + cg * 16]);
            ulonglong2 u0 = wp[0];
            ulonglong2 u1 = wp[1];
            ulonglong2 u2 = wp[2];
            ulonglong2 u3 = wp[3];
            asm("fma.rn.f32x2 %0, %1, %2, %0;" : "+l"(acc[0])  : "l"(aa0), "l"(u0.x));
            asm("fma.rn.f32x2 %0, %1, %2, %0;" : "+l"(acc[1])  : "l"(aa0), "l"(u0.y));
            asm("fma.rn.f32x2 %0, %1, %2, %0;" : "+l"(acc[2])  : "l"(aa0), "l"(u1.x));
            asm("fma.rn.f32x2 %0, %1, %2, %0;" : "+l"(acc[3])  : "l"(aa0), "l"(u1.y));
            asm("fma.rn.f32x2 %0, %1, %2, %0;" : "+l"(acc[4])  : "l"(aa0), "l"(u2.x));
            asm("fma.rn.f32x2 %0, %1, %2, %0;" : "+l"(acc[5])  : "l"(aa0), "l"(u2.y));
            asm("fma.rn.f32x2 %0, %1, %2, %0;" : "+l"(acc[6])  : "l"(aa0), "l"(u3.x));
            asm("fma.rn.f32x2 %0, %1, %2, %0;" : "+l"(acc[7])  : "l"(aa0), "l"(u3.y));
            asm("fma.rn.f32x2 %0, %1, %2, %0;" : "+l"(acc[8])  : "l"(aa1), "l"(u0.x));
            asm("fma.rn.f32x2 %0, %1, %2, %0;" : "+l"(acc[9])  : "l"(aa1), "l"(u0.y));
            asm("fma.rn.f32x2 %0, %1, %2, %0;" : "+l"(acc[10]) : "l"(aa1), "l"(u1.x));
            asm("fma.rn.f32x2 %0, %1, %2, %0;" : "+l"(acc[11]) : "l"(aa1), "l"(u1.y));
            asm("fma.rn.f32x2 %0, %1, %2, %0;" : "+l"(acc[12]) : "l"(aa1), "l"(u2.x));
            asm("fma.rn.f32x2 %0, %1, %2, %0;" : "+l"(acc[13]) : "l"(aa1), "l"(u2.y));
            asm("fma.rn.f32x2 %0, %1, %2, %0;" : "+l"(acc[14]) : "l"(aa1), "l"(u3.x));
            asm("fma.rn.f32x2 %0, %1, %2, %0;" : "+l"(acc[15]) : "l"(aa1), "l"(u3.y));
        }

        int gr0 = t * GBM + r0;
        int gr1 = gr0 + 64;
        if (gr0 < n) {
            float* dst = g_y + (size_t)gr0 * D + cg * 16;
            stg_el32B(dst,     acc[0], acc[1], acc[2],  acc[3]);
            stg_el32B(dst + 8, acc[4], acc[5], acc[6],  acc[7]);
        }
        if (gr1 < n) {
            float* dst = g_y + (size_t)gr1 * D + cg * 16;
            stg_el32B(dst,     acc[8],  acc[9],  acc[10], acc[11]);
            stg_el32B(dst + 8, acc[12], acc[13], acc[14], acc[15]);
        }

        __syncthreads();
        buf ^= 1;
    }
}

// ---------------------------------------------------------------------------
// K5: edge kernel on src-sorted edges. Consecutive edges share src -> y row
// served from L1 after first touch; cold y misses stream sequentially.
// x_in stays the lone random gather, L2-pinned via evict_last.
// ---------------------------------------------------------------------------
__global__ void __launch_bounds__(256) edge_sorted(
    const float* __restrict__ x_in,
    float* __restrict__ out,
    int E)
{
    const unsigned int gthread = blockIdx.x * blockDim.x + threadIdx.x;
    const int warp_id = (int)(gthread >> 5);
    const int lane = threadIdx.x & 31;
    const int half = lane >> 4;
    const int sub  = lane & 15;
    const int e    = warp_id * 2 + half;
    if (e >= E) return;

    int4 t = __ldg(&g_sorted[e]);              // (src, dst, eid, 0)

    // y row: plain cached loads (L1 reuse across the src group)
    const float4* yrow = (const float4*)(g_y + (size_t)t.x * D);
    float4 a0 = __ldg(yrow + sub * 2);
    float4 a1 = __ldg(yrow + sub * 2 + 1);

    float4 b0, b1;
    ldg_el32B(x_in + (size_t)t.y * D + sub * 8, b0, b1);

    float v = a0.x * b0.x + a0.y * b0.y + a0.z * b0.z + a0.w * b0.w
            + a1.x * b1.x + a1.y * b1.y + a1.z * b1.z + a1.w * b1.w;

    #pragma unroll
    for (int o = 8; o > 0; o >>= 1)
        v += __shfl_xor_sync(0xFFFFFFFFu, v, o);

    if (sub == 0)
        __stcs(&out[t.z], 1.0f / (1.0f + __expf(-v)));
}

// ---------------------------------------------------------------------------
// fallback unsorted edge kernel (used only if sizes exceed static buffers)
// ---------------------------------------------------------------------------
__global__ void __launch_bounds__(256) edge_bilinear(
    const float* __restrict__ x_in,
    const void* __restrict__ ei,
    float* __restrict__ out,
    int E)
{
    const unsigned int gthread = blockIdx.x * blockDim.x + threadIdx.x;
    const int warp_id = (int)(gthread >> 5);
    const int lane = threadIdx.x & 31;
    const int half = lane >> 4;
    const int sub  = lane & 15;
    const int e    = warp_id * 2 + half;
    if (e >= E) return;

    long long s, d;
    if (g_bad) {
        const int* p = (const int*)ei;
        s = __ldcs(&p[e]); d = __ldcs(&p[E + e]);
    } else {
        const long long* p = (const long long*)ei;
        s = __ldcs(&p[e]); d = __ldcs(&p[(long long)E + e]);
    }
    float4 a0, a1, b0, b1;
    ldg_el32B(g_y  + s * D + sub * 8, a0, a1);
    ldg_el32B(x_in + d * D + sub * 8, b0, b1);
    float v = a0.x * b0.x + a0.y * b0.y + a0.z * b0.z + a0.w * b0.w
            + a1.x * b1.x + a1.y * b1.y + a1.z * b1.z + a1.w * b1.w;
    #pragma unroll
    for (int o = 8; o > 0; o >>= 1)
        v += __shfl_xor_sync(0xFFFFFFFFu, v, o);
    if (sub == 0)
        __stcs(&out[e], 1.0f / (1.0f + __expf(-v)));
}

// ---------------------------------------------------------------------------
// Launch
// ---------------------------------------------------------------------------
#define GEMM_SMEM ((D * D + 2 * ASZ) * sizeof(float))

extern "C" void kernel_launch(void* const* d_in, const int* in_sizes, int n_in,
                              void* d_out, int out_size)
{
    int i_xin = 0, i_xout = 1, i_ei = 2, i_w = 3;

    if (n_in == 4) {
        int w_idx = -1, ei_idx = -1;
        for (int i = 0; i < 4; i++)
            if (in_sizes[i] == D * D) w_idx = i;
        int idx[3], c = 0;
        for (int i = 0; i < 4; i++) if (i != w_idx) idx[c++] = i;
        if (w_idx >= 0 && c == 3) {
            if (in_sizes[idx[0]] == in_sizes[idx[1]])      { i_xin = idx[0]; i_xout = idx[1]; ei_idx = idx[2]; }
            else if (in_sizes[idx[0]] == in_sizes[idx[2]]) { i_xin = idx[0]; i_xout = idx[2]; ei_idx = idx[1]; }
            else                                            { i_xin = idx[1]; i_xout = idx[2]; ei_idx = idx[0]; }
            i_w = w_idx; i_ei = ei_idx;
        }
    }

    const float* x_in  = (const float*)d_in[i_xin];
    const float* x_out = (const float*)d_in[i_xout];
    const void*  ei    = d_in[i_ei];
    const float* W     = (const float*)d_in[i_w];
    float*       out   = (float*)d_out;

    int n = in_sizes[i_xin] / D;
    if (n > MAX_NODES) n = MAX_NODES;
    int E = in_sizes[i_ei] / 2;

    static int smem_set = 0;
    if (!smem_set) {
        cudaFuncSetAttribute(gemm_xout_w, cudaFuncAttributeMaxDynamicSharedMemorySize,
                             (int)GEMM_SMEM);
        smem_set = 1;
    }

    bool sortable = (E <= MAX_EDGES);

    init_k<<<64, 256>>>((const unsigned int*)ei, in_sizes[i_ei] * 2, n);
    if (sortable) {
        hist_k<<<1024, 256>>>(ei, E);
        scan_k<<<1, 1024>>>(n);
        scatter_k<<<1024, 256>>>(ei, E);
    }

    gemm_xout_w<<<NSM, 512, GEMM_SMEM>>>(x_out, W, n);

    {
        long long total_threads = ((long long)E + 1) / 2 * 32;
        int blocks = (int)((total_threads + 255) / 256);
        if (sortable)
            edge_sorted<<<blocks, 256>>>(x_in, out, E);
        else
            edge_bilinear<<<blocks, 256>>>(x_in, ei, out, E);
    }
}